// round 17
// baseline (speedup 1.0000x reference)
#include <cuda_runtime.h>
#include <cuda_bf16.h>
#include <cstdint>

#define NN 16384
#define EE 262144
#define H1C 256
#define DD 512
#define NEG_SLOPE 0.2f

// ---------------- device scratch ----------------
__device__ uint32_t g_xp [NN * H1C];
__device__ uint32_t g_h0p[NN * H1C];
__device__ uint32_t g_h1p[(size_t)NN * DD];
__device__ float    g_g1[(size_t)NN * DD];
__device__ float    g_g2[(size_t)NN * DD];
__device__ uint4 g_wfcp[(H1C / 4) * H1C];
__device__ uint4 g_w1p [(H1C / 4) * DD];
__device__ uint4 g_w2p [(DD / 4) * DD];
__device__ float4 g_P1[H1C];
__device__ float2 g_P2[DD];

__device__ float g_al1[NN * 4];
__device__ float2 g_al2a[NN];
__device__ float2 g_al2b[NN];
__device__ __align__(16) int g_deg[NN];
__device__ int   g_cursor[NN];
__device__ __align__(16) int g_off[NN + 1];
__device__ int   g_esrc[EE];
__device__ float g_alpha1a[EE];     // SoA per-head alpha (dense 4B streams)
__device__ float g_alpha1b[EE];
__device__ float g_salpha1a[NN];
__device__ float g_salpha1b[NN];
__device__ float g_alpha2[EE];
__device__ float g_salpha2[NN];

// ---------------- streams / events ----------------
static cudaStream_t g_s1 = nullptr, g_s2 = nullptr;
static cudaEvent_t g_evF, g_evWFC, g_evWP, g_evG1, g_evJ1, g_evG2a,
                   g_evH0, g_evH1, g_evJ2, g_evA2H0;
namespace {
struct StreamInit {
    StreamInit() {
        cudaStreamCreateWithFlags(&g_s1, cudaStreamNonBlocking);
        cudaStreamCreateWithFlags(&g_s2, cudaStreamNonBlocking);
        cudaEventCreateWithFlags(&g_evF,    cudaEventDisableTiming);
        cudaEventCreateWithFlags(&g_evWFC,  cudaEventDisableTiming);
        cudaEventCreateWithFlags(&g_evWP,   cudaEventDisableTiming);
        cudaEventCreateWithFlags(&g_evG1,   cudaEventDisableTiming);
        cudaEventCreateWithFlags(&g_evJ1,   cudaEventDisableTiming);
        cudaEventCreateWithFlags(&g_evG2a,  cudaEventDisableTiming);
        cudaEventCreateWithFlags(&g_evH0,   cudaEventDisableTiming);
        cudaEventCreateWithFlags(&g_evH1,   cudaEventDisableTiming);
        cudaEventCreateWithFlags(&g_evJ2,   cudaEventDisableTiming);
        cudaEventCreateWithFlags(&g_evA2H0, cudaEventDisableTiming);
    }
};
static StreamInit g_si;
}

// ---------------- split helpers ----------------
__device__ __forceinline__ void split_pack(float x0, float x1,
                                           uint32_t& hi, uint32_t& lo) {
    __nv_bfloat16 h0 = __float2bfloat16_rn(x0);
    __nv_bfloat16 h1 = __float2bfloat16_rn(x1);
    hi = (uint32_t)__bfloat16_as_ushort(h0) |
         ((uint32_t)__bfloat16_as_ushort(h1) << 16);
    float l0 = x0 - __bfloat162float(h0);
    float l1 = x1 - __bfloat162float(h1);
    __nv_bfloat162 lp = __floats2bfloat162_rn(l0, l1);
    lo = *reinterpret_cast<const uint32_t*>(&lp);
}
__device__ __forceinline__ float bf_lo(uint32_t w) {
    return __bfloat162float(__ushort_as_bfloat16((unsigned short)(w & 0xffffu)));
}
__device__ __forceinline__ float bf_hi(uint32_t w) {
    return __bfloat162float(__ushort_as_bfloat16((unsigned short)(w >> 16)));
}

// ---------------- pack kernels ----------------
__global__ void pack_a_kernel(const float* __restrict__ X,
                              uint32_t* __restrict__ P, int npairs) {
    int i = blockIdx.x * blockDim.x + threadIdx.x;
    if (i < npairs) {
        float2 v = *(const float2*)(X + 2 * (size_t)i);
        split_pack(v.x, v.y, P[2 * (size_t)i], P[2 * (size_t)i + 1]);
    }
}
__global__ void pack_b_kernel(const float* __restrict__ W,
                              uint4* __restrict__ P, int K, int N) {
    int idx = blockIdx.x * blockDim.x + threadIdx.x;
    int total = (K / 4) * N;
    if (idx >= total) return;
    int c = idx / N;
    int n = idx - c * N;
    const float* wp = W + (size_t)(4 * c) * N + n;
    uint4 o;
    split_pack(wp[0], wp[N], o.x, o.y);
    split_pack(wp[2 * N], wp[3 * N], o.z, o.w);
    P[idx] = o;
}

// ---------------- projection kernels ----------------
__global__ void proj1_kernel(const float* __restrict__ W1,
                             const float* __restrict__ a1s,
                             const float* __restrict__ a1d) {
    int k = (blockIdx.x * blockDim.x + threadIdx.x) >> 5;
    if (k >= H1C) return;
    int lane = threadIdx.x & 31;
    const float* wr = W1 + (size_t)k * DD;
    float s0 = 0.f, s1 = 0.f, d0 = 0.f, d1 = 0.f;
    for (int c = lane; c < H1C; c += 32) {
        float w0 = wr[c];
        float w1 = wr[H1C + c];
        s0 = fmaf(w0, a1s[c], s0);
        s1 = fmaf(w1, a1s[H1C + c], s1);
        d0 = fmaf(w0, a1d[c], d0);
        d1 = fmaf(w1, a1d[H1C + c], d1);
    }
    #pragma unroll
    for (int o = 16; o; o >>= 1) {
        s0 += __shfl_down_sync(0xffffffffu, s0, o);
        s1 += __shfl_down_sync(0xffffffffu, s1, o);
        d0 += __shfl_down_sync(0xffffffffu, d0, o);
        d1 += __shfl_down_sync(0xffffffffu, d1, o);
    }
    if (lane == 0) g_P1[k] = make_float4(s0, s1, d0, d1);
}
__global__ void proj2_kernel(const float* __restrict__ W2,
                             const float* __restrict__ a2s,
                             const float* __restrict__ a2d) {
    int k = (blockIdx.x * blockDim.x + threadIdx.x) >> 5;
    if (k >= DD) return;
    int lane = threadIdx.x & 31;
    const float* wr = W2 + (size_t)k * DD;
    float s = 0.f, d = 0.f;
    for (int c = lane; c < DD; c += 32) {
        float w = wr[c];
        s = fmaf(w, a2s[c], s);
        d = fmaf(w, a2d[c], d);
    }
    #pragma unroll
    for (int o = 16; o; o >>= 1) {
        s += __shfl_down_sync(0xffffffffu, s, o);
        d += __shfl_down_sync(0xffffffffu, d, o);
    }
    if (lane == 0) g_P2[k] = make_float2(s, d);
}

// ---------------- CSR ----------------
__global__ void zero_kernel() {
    int i = blockIdx.x * blockDim.x + threadIdx.x;
    if (i < NN) { g_deg[i] = 0; g_cursor[i] = 0; }
}
__global__ void count_kernel(const int* __restrict__ adj) {
    int i = blockIdx.x * blockDim.x + threadIdx.x;
    if (i < EE) atomicAdd(&g_deg[adj[EE + i]], 1);
}
__global__ void scan_kernel() {
    int t = threadIdx.x;
    int4 v[16];
    const int4* dp = (const int4*)g_deg + t * 16;
    #pragma unroll
    for (int k = 0; k < 16; k++) v[k] = dp[k];
    int sum = 0;
    #pragma unroll
    for (int k = 0; k < 16; k++) sum += v[k].x + v[k].y + v[k].z + v[k].w;
    __shared__ int part[256];
    part[t] = sum;
    __syncthreads();
    for (int s = 1; s < 256; s <<= 1) {
        int q = (t >= s) ? part[t - s] : 0;
        __syncthreads();
        part[t] += q;
        __syncthreads();
    }
    int run = (t > 0) ? part[t - 1] : 0;
    int4* op = (int4*)g_off + t * 16;
    #pragma unroll
    for (int k = 0; k < 16; k++) {
        int4 o;
        o.x = run; run += v[k].x;
        o.y = run; run += v[k].y;
        o.z = run; run += v[k].z;
        o.w = run; run += v[k].w;
        op[k] = o;
    }
    if (t == 255) g_off[NN] = run;
}
__global__ void scatter_kernel(const int* __restrict__ adj) {
    int i = blockIdx.x * blockDim.x + threadIdx.x;
    if (i < EE) {
        int src = adj[i];
        int dst = adj[EE + i];
        int p = g_off[dst] + atomicAdd(&g_cursor[dst], 1);
        g_esrc[p] = src;
    }
}

// ================= Tensor-core GEMM (bf16x3, cp.async pipeline) =================
__device__ __forceinline__ int smw(int outer, int kw) {
    int line = outer >> 1;
    int M = ((line & 3) << 1) | ((line >> 2) & 1);
    int lc = ((outer & 1) << 2) + (kw >> 1);
    return line * 32 + (((lc ^ M) << 2) | ((kw & 1) << 1));
}
__device__ __forceinline__ void mma16816(float* d, const uint32_t* a,
                                         const uint32_t* b) {
    asm volatile(
        "mma.sync.aligned.m16n8k16.row.col.f32.bf16.bf16.f32 "
        "{%0,%1,%2,%3}, {%4,%5,%6,%7}, {%8,%9}, {%0,%1,%2,%3};\n"
        : "+f"(d[0]), "+f"(d[1]), "+f"(d[2]), "+f"(d[3])
        : "r"(a[0]), "r"(a[1]), "r"(a[2]), "r"(a[3]),
          "r"(b[0]), "r"(b[1]));
}
__device__ __forceinline__ uint32_t smem_u32(const void* p) {
    uint32_t a;
    asm("{ .reg .u64 t; cvta.to.shared.u64 t, %1; cvt.u32.u64 %0, t; }"
        : "=r"(a) : "l"(p));
    return a;
}
__device__ __forceinline__ void cp16(uint32_t dst, const void* src) {
    asm volatile("cp.async.cg.shared.global [%0], [%1], 16;"
                 :: "r"(dst), "l"(src));
}
#define CP_COMMIT() asm volatile("cp.async.commit_group;" ::: "memory")
#define STG_BYTES 16384
#define NSTG 4

__device__ __forceinline__ void fill_stage(
    const uint32_t* __restrict__ Ap, const uint4* __restrict__ Bp,
    int brow, int bcol, int lda, int N, int k0, int tid, uint32_t sbase)
{
    int c4 = tid & 3;
    #pragma unroll
    for (int f = 0; f < 2; f++) {
        int row = (tid >> 2) + 64 * f;
        cp16(sbase + 4 * smw(row, 2 * c4),
             Ap + (size_t)(brow + row) * lda + k0 + 4 * c4);
    }
    int tc = tid >> 6;
    int m  = tid & 63;
    const uint4* bp = Bp + (size_t)((k0 >> 2) + tc) * N + bcol + 2 * m;
    uint32_t bB = sbase + 8192;
    cp16(bB + 4 * smw(2 * m,     2 * tc), bp);
    cp16(bB + 4 * smw(2 * m + 1, 2 * tc), bp + 1);
}

// OUT_MODE: 0 = fp32 write, 1 = packed split-bf16 w/ bias+relu, 2 = fp32 accumulate
template <int OUT_MODE>
__global__ __launch_bounds__(256, 2) void tgemm_p_kernel(
    const uint32_t* __restrict__ Ap, const uint4* __restrict__ Bp,
    const float* __restrict__ bias, void* __restrict__ Cout,
    int M, int N, int K, int lda)
{
    extern __shared__ uint32_t dynsm[];
    const uint32_t sb = smem_u32(dynsm);

    const int tid  = threadIdx.x;
    const int lane = tid & 31;
    const int wid  = tid >> 5;
    const int wm   = wid & 1;
    const int wn   = wid >> 1;
    const int brow = blockIdx.y * 128;
    const int bcol = blockIdx.x * 128;

    float acc[4][4][4];
    #pragma unroll
    for (int i = 0; i < 4; i++)
        #pragma unroll
        for (int j = 0; j < 4; j++)
            #pragma unroll
            for (int q = 0; q < 4; q++) acc[i][j][q] = 0.f;

    const int iters = K >> 4;

    #pragma unroll
    for (int s = 0; s < NSTG - 1; s++) {
        if (s < iters) {
            fill_stage(Ap, Bp, brow, bcol, lda, N, s << 4, tid, sb + s * STG_BYTES);
            CP_COMMIT();
        }
    }

    const int c  = lane & 3;
    const int r4 = lane >> 2;
    const int offA0 = smw(r4, c);
    const int offA1 = smw(8 + r4, c);
    const int offA2 = smw(r4, c + 4);
    const int offA3 = smw(8 + r4, c + 4);

    for (int it = 0; it < iters; ++it) {
        int rem = iters - 1 - it;
        if (rem >= 2)      asm volatile("cp.async.wait_group 2;" ::: "memory");
        else if (rem == 1) asm volatile("cp.async.wait_group 1;" ::: "memory");
        else               asm volatile("cp.async.wait_group 0;" ::: "memory");
        __syncthreads();

        uint32_t* buf  = dynsm + (it & (NSTG - 1)) * 4096;
        uint32_t* Abuf = buf;
        uint32_t* Bbuf = buf + 2048;

        uint2 bfr[4][2];
        #pragma unroll
        for (int ni = 0; ni < 4; ni++) {
            int base = wn * 512;
            bfr[ni][0] = *(const uint2*)&Bbuf[base + smw(ni * 8 + r4, c)];
            bfr[ni][1] = *(const uint2*)&Bbuf[base + smw(ni * 8 + r4, c + 4)];
        }
        #pragma unroll
        for (int mi = 0; mi < 4; mi++) {
            int base = (wm * 64 + mi * 16) * 16;
            uint2 a0 = *(const uint2*)&Abuf[base + offA0];
            uint2 a1 = *(const uint2*)&Abuf[base + offA1];
            uint2 a2 = *(const uint2*)&Abuf[base + offA2];
            uint2 a3 = *(const uint2*)&Abuf[base + offA3];
            uint32_t ah[4] = {a0.x, a1.x, a2.x, a3.x};
            uint32_t al[4] = {a0.y, a1.y, a2.y, a3.y};
            #pragma unroll
            for (int ni = 0; ni < 4; ni++) {
                uint32_t bh[2] = {bfr[ni][0].x, bfr[ni][1].x};
                uint32_t bl[2] = {bfr[ni][0].y, bfr[ni][1].y};
                mma16816(acc[mi][ni], ah, bh);
                mma16816(acc[mi][ni], ah, bl);
                mma16816(acc[mi][ni], al, bh);
            }
        }

        if (it + NSTG - 1 < iters) {
            fill_stage(Ap, Bp, brow, bcol, lda, N, (it + NSTG - 1) << 4, tid,
                       sb + ((it + NSTG - 1) & (NSTG - 1)) * STG_BYTES);
            CP_COMMIT();
        }
    }

    #pragma unroll
    for (int mi = 0; mi < 4; mi++) {
        int row = brow + wm * 64 + mi * 16 + r4;
        #pragma unroll
        for (int ni = 0; ni < 4; ni++) {
            int col = bcol + wn * 32 + ni * 8 + 2 * c;
            float2 v0 = make_float2(acc[mi][ni][0], acc[mi][ni][1]);
            float2 v1 = make_float2(acc[mi][ni][2], acc[mi][ni][3]);
            if (OUT_MODE == 1) {
                float2 bb = *(const float2*)(bias + col);
                v0.x = fmaxf(v0.x + bb.x, 0.f); v0.y = fmaxf(v0.y + bb.y, 0.f);
                v1.x = fmaxf(v1.x + bb.x, 0.f); v1.y = fmaxf(v1.y + bb.y, 0.f);
                uint2 w0, w1;
                split_pack(v0.x, v0.y, w0.x, w0.y);
                split_pack(v1.x, v1.y, w1.x, w1.y);
                uint32_t* P = (uint32_t*)Cout;
                *(uint2*)(P + (size_t)row * N + col)       = w0;
                *(uint2*)(P + (size_t)(row + 8) * N + col) = w1;
            } else {
                float* C = (float*)Cout;
                float* c0 = C + (size_t)row * N + col;
                float* c1 = C + (size_t)(row + 8) * N + col;
                if (OUT_MODE == 2) {
                    float2 o0 = *(float2*)c0;
                    float2 o1 = *(float2*)c1;
                    v0.x += o0.x; v0.y += o0.y;
                    v1.x += o1.x; v1.y += o1.y;
                }
                *(float2*)c0 = v0;
                *(float2*)c1 = v1;
            }
        }
    }
}

// ---------------- attention scalars from packed h via projections ----------------
__global__ void al1p_kernel() {
    int n = (blockIdx.x * blockDim.x + threadIdx.x) >> 5;
    if (n >= NN) return;
    int lane = threadIdx.x & 31;
    const uint2* row = (const uint2*)(g_h0p + (size_t)n * H1C);
    float s0 = 0.f, s1 = 0.f, d0 = 0.f, d1 = 0.f;
    for (int i = lane; i < 128; i += 32) {
        uint2 w = row[i];
        float x0 = bf_lo(w.x) + bf_lo(w.y);
        float x1 = bf_hi(w.x) + bf_hi(w.y);
        float4 p0 = g_P1[2 * i];
        float4 p1 = g_P1[2 * i + 1];
        s0 += x0 * p0.x + x1 * p1.x;
        s1 += x0 * p0.y + x1 * p1.y;
        d0 += x0 * p0.z + x1 * p1.z;
        d1 += x0 * p0.w + x1 * p1.w;
    }
    #pragma unroll
    for (int o = 16; o; o >>= 1) {
        s0 += __shfl_down_sync(0xffffffffu, s0, o);
        s1 += __shfl_down_sync(0xffffffffu, s1, o);
        d0 += __shfl_down_sync(0xffffffffu, d0, o);
        d1 += __shfl_down_sync(0xffffffffu, d1, o);
    }
    if (lane == 0) ((float4*)g_al1)[n] = make_float4(s0, s1, d0, d1);
}

__global__ void al2h_kernel(int half, float2* __restrict__ outv) {
    int n = (blockIdx.x * blockDim.x + threadIdx.x) >> 5;
    if (n >= NN) return;
    int lane = threadIdx.x & 31;
    const uint2* row = (const uint2*)(g_h1p + (size_t)n * DD + half * H1C);
    const float2* P = g_P2 + half * H1C;
    float s = 0.f, d = 0.f;
    for (int i = lane; i < 128; i += 32) {
        uint2 w = row[i];
        float x0 = bf_lo(w.x) + bf_lo(w.y);
        float x1 = bf_hi(w.x) + bf_hi(w.y);
        float2 p0 = P[2 * i];
        float2 p1 = P[2 * i + 1];
        s += x0 * p0.x + x1 * p1.x;
        d += x0 * p0.y + x1 * p1.y;
    }
    #pragma unroll
    for (int o = 16; o; o >>= 1) {
        s += __shfl_down_sync(0xffffffffu, s, o);
        d += __shfl_down_sync(0xffffffffu, d, o);
    }
    if (lane == 0) outv[n] = make_float2(s, d);
}

__device__ __forceinline__ float lrelu(float x) {
    return x > 0.f ? x : NEG_SLOPE * x;
}

// ---------------- edge softmax ----------------
__global__ void alpha1_kernel() {
    int n = (blockIdx.x * blockDim.x + threadIdx.x) >> 5;
    if (n >= NN) return;
    int lane = threadIdx.x & 31;
    int o = g_off[n];
    int cnt = g_off[n + 1] - o;
    float dd0 = g_al1[n * 4 + 2];
    float dd1 = g_al1[n * 4 + 3];

    float m0 = -1e30f, m1 = -1e30f;
    for (int i = lane; i <= cnt; i += 32) {
        int s = (i < cnt) ? g_esrc[o + i] : n;
        m0 = fmaxf(m0, lrelu(g_al1[s * 4 + 0] + dd0));
        m1 = fmaxf(m1, lrelu(g_al1[s * 4 + 1] + dd1));
    }
    #pragma unroll
    for (int x = 16; x; x >>= 1) {
        m0 = fmaxf(m0, __shfl_xor_sync(0xffffffffu, m0, x));
        m1 = fmaxf(m1, __shfl_xor_sync(0xffffffffu, m1, x));
    }
    float sum0 = 0.f, sum1 = 0.f;
    for (int i = lane; i <= cnt; i += 32) {
        int s = (i < cnt) ? g_esrc[o + i] : n;
        sum0 += expf(lrelu(g_al1[s * 4 + 0] + dd0) - m0);
        sum1 += expf(lrelu(g_al1[s * 4 + 1] + dd1) - m1);
    }
    #pragma unroll
    for (int x = 16; x; x >>= 1) {
        sum0 += __shfl_xor_sync(0xffffffffu, sum0, x);
        sum1 += __shfl_xor_sync(0xffffffffu, sum1, x);
    }
    float inv0 = 1.f / (sum0 + 1e-16f);
    float inv1 = 1.f / (sum1 + 1e-16f);
    for (int i = lane; i <= cnt; i += 32) {
        int s = (i < cnt) ? g_esrc[o + i] : n;
        float a0 = expf(lrelu(g_al1[s * 4 + 0] + dd0) - m0) * inv0;
        float a1 = expf(lrelu(g_al1[s * 4 + 1] + dd1) - m1) * inv1;
        if (i < cnt) {
            g_alpha1a[o + i] = a0;
            g_alpha1b[o + i] = a1;
        } else {
            g_salpha1a[n] = a0;
            g_salpha1b[n] = a1;
        }
    }
}

__global__ void alpha2_kernel() {
    int n = (blockIdx.x * blockDim.x + threadIdx.x) >> 5;
    if (n >= NN) return;
    int lane = threadIdx.x & 31;
    int o = g_off[n];
    int cnt = g_off[n + 1] - o;
    float2 va = g_al2a[n];
    float2 vb = g_al2b[n];
    float dd = va.y + vb.y;

    float m = -1e30f;
    for (int i = lane; i <= cnt; i += 32) {
        int s = (i < cnt) ? g_esrc[o + i] : n;
        float sv = g_al2a[s].x + g_al2b[s].x;
        m = fmaxf(m, lrelu(sv + dd));
    }
    #pragma unroll
    for (int x = 16; x; x >>= 1)
        m = fmaxf(m, __shfl_xor_sync(0xffffffffu, m, x));
    float sum = 0.f;
    for (int i = lane; i <= cnt; i += 32) {
        int s = (i < cnt) ? g_esrc[o + i] : n;
        float sv = g_al2a[s].x + g_al2b[s].x;
        sum += expf(lrelu(sv + dd) - m);
    }
    #pragma unroll
    for (int x = 16; x; x >>= 1)
        sum += __shfl_xor_sync(0xffffffffu, sum, x);
    float inv = 1.f / (sum + 1e-16f);
    for (int i = lane; i <= cnt; i += 32) {
        int s = (i < cnt) ? g_esrc[o + i] : n;
        float sv = g_al2a[s].x + g_al2b[s].x;
        float a = expf(lrelu(sv + dd) - m) * inv;
        if (i < cnt) g_alpha2[o + i] = a;
        else g_salpha2[n] = a;
    }
}

// ---------------- aggregation halves ----------------
__global__ __launch_bounds__(64) void agg1h_kernel(const float* __restrict__ b1,
                                                   int head) {
    int n = blockIdx.x;
    int tid = threadIdx.x;
    int o = g_off[n];
    int cnt = g_off[n + 1] - o;

    __shared__ int   ssrc[64];
    __shared__ float sal[64];

    const float* alp  = head ? g_alpha1b : g_alpha1a;
    const float* salp = head ? g_salpha1b : g_salpha1a;
    const float* gbase = g_g1 + (size_t)head * H1C;
    float4 acc = make_float4(0.f, 0.f, 0.f, 0.f);
    for (int base = 0; base < cnt; base += 64) {
        int m = min(64, cnt - base);
        if (tid < m) {
            int e = o + base + tid;
            ssrc[tid] = g_esrc[e];
            sal[tid] = alp[e];
        }
        __syncthreads();
        #pragma unroll 4
        for (int j = 0; j < m; j++) {
            float a = sal[j];
            float4 v = ((const float4*)(gbase + (size_t)ssrc[j] * DD))[tid];
            acc.x = fmaf(a, v.x, acc.x);
            acc.y = fmaf(a, v.y, acc.y);
            acc.z = fmaf(a, v.z, acc.z);
            acc.w = fmaf(a, v.w, acc.w);
        }
        __syncthreads();
    }
    {
        float a = salp[n];
        float4 v = ((const float4*)(gbase + (size_t)n * DD))[tid];
        acc.x = fmaf(a, v.x, acc.x);
        acc.y = fmaf(a, v.y, acc.y);
        acc.z = fmaf(a, v.z, acc.z);
        acc.w = fmaf(a, v.w, acc.w);
    }
    float4 bb = ((const float4*)(b1 + head * H1C))[tid];
    acc.x = fmaxf(acc.x + bb.x, 0.f);
    acc.y = fmaxf(acc.y + bb.y, 0.f);
    acc.z = fmaxf(acc.z + bb.z, 0.f);
    acc.w = fmaxf(acc.w + bb.w, 0.f);
    uint4 w;
    split_pack(acc.x, acc.y, w.x, w.y);
    split_pack(acc.z, acc.w, w.z, w.w);
    *(uint4*)(g_h1p + (size_t)n * DD + head * H1C + 4 * tid) = w;
}

__global__ __launch_bounds__(64) void agg2h_kernel(const float* __restrict__ b2,
                                                   float* __restrict__ out,
                                                   int half) {
    int n = blockIdx.x;
    int tid = threadIdx.x;
    int o = g_off[n];
    int cnt = g_off[n + 1] - o;

    __shared__ int   ssrc[64];
    __shared__ float sal[64];

    const float* gbase = g_g2 + (size_t)half * H1C;
    float4 acc = make_float4(0.f, 0.f, 0.f, 0.f);
    for (int base = 0; base < cnt; base += 64) {
        int m = min(64, cnt - base);
        if (tid < m) {
            ssrc[tid] = g_esrc[o + base + tid];
            sal[tid] = g_alpha2[o + base + tid];
        }
        __syncthreads();
        #pragma unroll 4
        for (int j = 0; j < m; j++) {
            float a = sal[j];
            float4 v = ((const float4*)(gbase + (size_t)ssrc[j] * DD))[tid];
            acc.x = fmaf(a, v.x, acc.x);
            acc.y = fmaf(a, v.y, acc.y);
            acc.z = fmaf(a, v.z, acc.z);
            acc.w = fmaf(a, v.w, acc.w);
        }
        __syncthreads();
    }
    {
        float a = g_salpha2[n];
        float4 v = ((const float4*)(gbase + (size_t)n * DD))[tid];
        acc.x = fmaf(a, v.x, acc.x);
        acc.y = fmaf(a, v.y, acc.y);
        acc.z = fmaf(a, v.z, acc.z);
        acc.w = fmaf(a, v.w, acc.w);
    }
    float4 bb = ((const float4*)(b2 + half * H1C))[tid];
    acc.x = fmaxf(acc.x + bb.x, 0.f);
    acc.y = fmaxf(acc.y + bb.y, 0.f);
    acc.z = fmaxf(acc.z + bb.z, 0.f);
    acc.w = fmaxf(acc.w + bb.w, 0.f);
    *(float4*)(out + (size_t)n * DD + half * H1C + 4 * tid) = acc;
}

__global__ void join_kernel() {}

// ---------------- launcher ----------------
template <typename T>
static T* sym_p(const void* sym) {
    void* p = nullptr;
    cudaGetSymbolAddress(&p, sym);
    return (T*)p;
}

extern "C" void kernel_launch(void* const* d_in, const int* in_sizes, int n_in,
                              void* d_out, int out_size) {
    const float* x      = (const float*)d_in[0];
    const int*   adj    = (const int*)d_in[1];
    const float* W_fc   = (const float*)d_in[2];
    const float* b_fc   = (const float*)d_in[3];
    const float* W1     = (const float*)d_in[4];
    const float* a1_src = (const float*)d_in[5];
    const float* a1_dst = (const float*)d_in[6];
    const float* b1     = (const float*)d_in[7];
    const float* W2     = (const float*)d_in[8];
    const float* a2_src = (const float*)d_in[9];
    const float* a2_dst = (const float*)d_in[10];
    const float* b2     = (const float*)d_in[11];
    float* out = (float*)d_out;

    uint32_t* p_xp  = sym_p<uint32_t>(g_xp);
    uint32_t* p_h0p = sym_p<uint32_t>(g_h0p);
    uint32_t* p_h1p = sym_p<uint32_t>(g_h1p);
    float*    p_g1  = sym_p<float>(g_g1);
    float*    p_g2  = sym_p<float>(g_g2);
    uint4*    p_wfc = sym_p<uint4>(g_wfcp);
    uint4*    p_w1  = sym_p<uint4>(g_w1p);
    uint4*    p_w2  = sym_p<uint4>(g_w2p);
    float2*   p_a2a = sym_p<float2>(g_al2a);
    float2*   p_a2b = sym_p<float2>(g_al2b);

    const int dyn = NSTG * STG_BYTES;   // 64 KB
    cudaFuncSetAttribute(tgemm_p_kernel<0>,
                         cudaFuncAttributeMaxDynamicSharedMemorySize, dyn);
    cudaFuncSetAttribute(tgemm_p_kernel<1>,
                         cudaFuncAttributeMaxDynamicSharedMemorySize, dyn);
    cudaFuncSetAttribute(tgemm_p_kernel<2>,
                         cudaFuncAttributeMaxDynamicSharedMemorySize, dyn);

    // fork events
    cudaEventRecord(g_evF, 0);
    cudaStreamWaitEvent(g_s1, g_evF, 0);
    cudaStreamWaitEvent(g_s2, g_evF, 0);

    // launches 1-5 (ncu -s 5 skips these), launch 6 = GEMM1 (profiled)
    pack_a_kernel<<<(NN * H1C / 2 + 255) / 256, 256>>>(x, p_xp, NN * H1C / 2);      // 1 main
    pack_b_kernel<<<((H1C / 4) * H1C + 255) / 256, 256, 0, g_s2>>>(W_fc, p_wfc, H1C, H1C); // 2 s2
    cudaEventRecord(g_evWFC, g_s2);
    pack_b_kernel<<<((H1C / 4) * DD + 255) / 256, 256, 0, g_s1>>>(W1, p_w1, H1C, DD); // 3 s1
    cudaEventRecord(g_evWP, g_s1);
    proj1_kernel<<<(H1C * 32 + 255) / 256, 256, 0, g_s1>>>(W1, a1_src, a1_dst);     // 4 s1
    proj2_kernel<<<(DD * 32 + 255) / 256, 256, 0, g_s1>>>(W2, a2_src, a2_dst);      // 5 s1
    cudaStreamWaitEvent(0, g_evWFC, 0);
    tgemm_p_kernel<1><<<dim3(H1C / 128, NN / 128), 256, dyn>>>(                     // 6 main (profiled)
        p_xp, p_wfc, b_fc, p_h0p, NN, H1C, H1C, H1C);
    cudaEventRecord(g_evG1, 0);

    // s1: rest of setup branch (W2 pack + CSR), then al1/alpha1
    pack_b_kernel<<<((DD / 4) * DD + 255) / 256, 256, 0, g_s1>>>(W2, p_w2, DD, DD);
    zero_kernel<<<(NN + 255) / 256, 256, 0, g_s1>>>();
    count_kernel<<<(EE + 255) / 256, 256, 0, g_s1>>>(adj);
    scan_kernel<<<1, 256, 0, g_s1>>>();
    scatter_kernel<<<(EE + 255) / 256, 256, 0, g_s1>>>(adj);
    cudaStreamWaitEvent(g_s1, g_evG1, 0);
    al1p_kernel<<<(NN * 32 + 255) / 256, 256, 0, g_s1>>>();
    alpha1_kernel<<<(NN * 32 + 255) / 256, 256, 0, g_s1>>>();
    cudaEventRecord(g_evJ1, g_s1);

    // main: GEMM2 column halves (needs W1 pack from s1)
    cudaStreamWaitEvent(0, g_evWP, 0);
    tgemm_p_kernel<0><<<dim3(2, NN / 128), 256, dyn>>>(
        p_h0p, p_w1, nullptr, p_g1, NN, DD, H1C, H1C);
    cudaEventRecord(g_evG2a, 0);
    tgemm_p_kernel<0><<<dim3(2, NN / 128), 256, dyn>>>(
        p_h0p, p_w1 + H1C, nullptr, p_g1 + H1C, NN, DD, H1C, H1C);

    // s1: agg1 head0 (h1p K-half0), then G3(N0,K0)
    cudaStreamWaitEvent(g_s1, g_evG2a, 0);
    agg1h_kernel<<<NN, 64, 0, g_s1>>>(b1, 0);
    cudaEventRecord(g_evH0, g_s1);
    tgemm_p_kernel<0><<<dim3(2, NN / 128), 256, dyn, g_s1>>>(
        p_h1p, p_w2, nullptr, p_g2, NN, DD, H1C, DD);

    // s2: al2 half0 as soon as h1p K-half0 exists
    cudaStreamWaitEvent(g_s2, g_evH0, 0);
    al2h_kernel<<<(NN * 32 + 255) / 256, 256, 0, g_s2>>>(0, p_a2a);

    // main: agg1 head1 (after GEMM2b on main; alpha1 via evJ1)
    cudaStreamWaitEvent(0, g_evJ1, 0);
    agg1h_kernel<<<NN, 64>>>(b1, 1);
    cudaEventRecord(g_evH1, 0);

    // s2: al2 half1 + alpha2
    cudaStreamWaitEvent(g_s2, g_evH1, 0);
    al2h_kernel<<<(NN * 32 + 255) / 256, 256, 0, g_s2>>>(1, p_a2b);
    alpha2_kernel<<<(NN * 32 + 255) / 256, 256, 0, g_s2>>>();
    cudaEventRecord(g_evJ2, g_s2);

    // s1: G3(N0,K1) accumulate — needs h1p K-half1
    cudaStreamWaitEvent(g_s1, g_evH1, 0);
    tgemm_p_kernel<2><<<dim3(2, NN / 128), 256, dyn, g_s1>>>(
        p_h1p + H1C, p_w2 + (size_t)(H1C / 4) * DD, nullptr, p_g2,
        NN, DD, H1C, DD);

    // main: G3(N1,K0) then G3(N1,K1) accumulate
    cudaStreamWaitEvent(0, g_evH0, 0);
    tgemm_p_kernel<0><<<dim3(2, NN / 128), 256, dyn>>>(
        p_h1p, p_w2 + H1C, nullptr, p_g2 + H1C, NN, DD, H1C, DD);
    tgemm_p_kernel<2><<<dim3(2, NN / 128), 256, dyn>>>(
        p_h1p + H1C, p_w2 + (size_t)(H1C / 4) * DD + H1C, nullptr, p_g2 + H1C,
        NN, DD, H1C, DD);

    // s1: agg2 half0 (g2 N0 complete on s1) — needs alpha2
    cudaStreamWaitEvent(g_s1, g_evJ2, 0);
    agg2h_kernel<<<NN, 64, 0, g_s1>>>(b2, out, 0);
    cudaEventRecord(g_evA2H0, g_s1);

    // main: agg2 half1, then join all branches
    cudaStreamWaitEvent(0, g_evJ2, 0);
    agg2h_kernel<<<NN, 64>>>(b2, out, 1);
    cudaStreamWaitEvent(0, g_evA2H0, 0);
    join_kernel<<<1, 32>>>();
}